// round 2
// baseline (speedup 1.0000x reference)
#include <cuda_runtime.h>
#include <math.h>

#define NCLS   1000
#define NROWS  65536
#define EPSF   1e-6f
#define WARPS_PER_BLK 8
#define THREADS 256
#define GRID_BLKS (NROWS / WARPS_PER_BLK)

// Global accumulators — zero-initialized at load; the finalizing (last) block
// resets them after each launch so graph replays are deterministic.
__device__ double g_S3 = 0.0;            // unlabeled rows: sum of -log(prod u^idx)
__device__ double g_S2 = 0.0;            // labeled rows:  sum of p*(log(u_lab)-C0)
__device__ double g_CE = 0.0;            // labeled rows:  sum of -logsoftmax[lab]
__device__ unsigned long long g_nP = 0ull;
__device__ unsigned int g_done = 0u;

__global__ __launch_bounds__(THREADS)
void mpuloss_fused(const float* __restrict__ outputs,
                   const int*   __restrict__ labels,
                   const float* __restrict__ prior,
                   const int*   __restrict__ indexlist,
                   float* __restrict__ out, int out_size) {
    __shared__ float  s_idx[NCLS];
    __shared__ double sh3[WARPS_PER_BLK], sh2[WARPS_PER_BLK], shc[WARPS_PER_BLK];
    __shared__ int    shn[WARPS_PER_BLK];
    __shared__ float  s_red[WARPS_PER_BLK];
    __shared__ bool   s_last;

    const int tid = threadIdx.x;
    for (int i = tid; i < NCLS; i += THREADS) s_idx[i] = (float)indexlist[i];
    __syncthreads();

    const int warp = tid >> 5;
    const int lane = tid & 31;
    const int row  = blockIdx.x * WARPS_PER_BLK + warp;
    const float* xrow = outputs + (size_t)row * NCLS;

    const int  lab     = labels[row];
    const bool labeled = (lab <= NCLS - 1);

    // ---- load full row into registers (250 float4 across 32 lanes) ----
    float4 v[8];
    #pragma unroll
    for (int i = 0; i < 8; i++) {
        const int q = i * 32 + lane;
        if (q < 250) v[i] = reinterpret_cast<const float4*>(xrow)[q];
        else         v[i] = make_float4(-INFINITY, -INFINITY, -INFINITY, -INFINITY);
    }

    // ---- row max ----
    float mx = -INFINITY;
    #pragma unroll
    for (int i = 0; i < 8; i++)
        mx = fmaxf(mx, fmaxf(fmaxf(v[i].x, v[i].y), fmaxf(v[i].z, v[i].w)));

    // capture x[lab] before overwriting registers
    float xlab = 0.0f;
    if (labeled) {
        const int ql = lab >> 2;
        #pragma unroll
        for (int i = 0; i < 8; i++) {
            const int q = i * 32 + lane;
            if (q == ql) {
                xlab = (lab & 2) ? ((lab & 1) ? v[i].w : v[i].z)
                                 : ((lab & 1) ? v[i].y : v[i].x);
            }
        }
    }

    #pragma unroll
    for (int o = 16; o; o >>= 1) mx = fmaxf(mx, __shfl_xor_sync(0xffffffffu, mx, o));
    #pragma unroll
    for (int o = 16; o; o >>= 1) xlab += __shfl_xor_sync(0xffffffffu, xlab, o);

    // ---- exp pass + Z ----
    const float L2E = 1.4426950408889634f;
    float z = 0.0f;
    #pragma unroll
    for (int i = 0; i < 8; i++) {
        const int q = i * 32 + lane;
        if (q < 250) {
            v[i].x = exp2f((v[i].x - mx) * L2E);
            v[i].y = exp2f((v[i].y - mx) * L2E);
            v[i].z = exp2f((v[i].z - mx) * L2E);
            v[i].w = exp2f((v[i].w - mx) * L2E);
            z += (v[i].x + v[i].y) + (v[i].z + v[i].w);
        }
    }
    #pragma unroll
    for (int o = 16; o; o >>= 1) z += __shfl_xor_sync(0xffffffffu, z, o);

    double wS3 = 0.0, wS2 = 0.0, wCE = 0.0;

    if (!labeled) {
        // pu3 term via product identity: sum_c -log(u_c)*idx_c = -log(prod u_c^idx_c)
        // u = (1-soft)+eps in [~0.97, 1]; fma(idx, u-1, 1) selects u or 1 exactly
        // (u-1 is Sterbenz-exact). Product stays in [~0.3, 1] — no MUFU in the loop.
        const float invZ = 1.0f / z;
        float prod = 1.0f;
        #pragma unroll
        for (int i = 0; i < 8; i++) {
            const int q = i * 32 + lane;
            if (q < 250) {
                const float4 id = *reinterpret_cast<const float4*>(&s_idx[q * 4]);
                float s, u;
                s = v[i].x * invZ; u = (1.0f - s) + EPSF; prod *= fmaf(id.x, u - 1.0f, 1.0f);
                s = v[i].y * invZ; u = (1.0f - s) + EPSF; prod *= fmaf(id.y, u - 1.0f, 1.0f);
                s = v[i].z * invZ; u = (1.0f - s) + EPSF; prod *= fmaf(id.z, u - 1.0f, 1.0f);
                s = v[i].w * invZ; u = (1.0f - s) + EPSF; prod *= fmaf(id.w, u - 1.0f, 1.0f);
            }
        }
        #pragma unroll
        for (int o = 16; o; o >>= 1) prod *= __shfl_xor_sync(0xffffffffu, prod, o);
        if (lane == 0) wS3 = -(double)logf(prod);
    } else if (lane == 0) {
        // pu2 per-row contribution minus the constant C0*sumPrior (added in finalize):
        //   p*(log((1-slab)+eps) - C0)
        const float elab = exp2f((xlab - mx) * L2E);
        const float slab = elab / z;
        const float p    = __ldg(prior + lab);
        const float C0   = logf(1.0f + EPSF);
        wS2 = (double)(p * (logf((1.0f - slab) + EPSF) - C0));
        wCE = (double)(-(xlab - mx - __logf(z)));
    }

    if (lane == 0) {
        sh3[warp] = wS3; sh2[warp] = wS2; shc[warp] = wCE;
        shn[warp] = labeled ? 1 : 0;
    }
    __syncthreads();

    if (tid == 0) {
        double a = 0.0, b = 0.0, c = 0.0; int n = 0;
        #pragma unroll
        for (int i = 0; i < WARPS_PER_BLK; i++) {
            a += sh3[i]; b += sh2[i]; c += shc[i]; n += shn[i];
        }
        atomicAdd(&g_S3, a);
        atomicAdd(&g_S2, b);
        atomicAdd(&g_CE, c);
        atomicAdd(&g_nP, (unsigned long long)n);
        __threadfence();
        s_last = (atomicAdd(&g_done, 1u) == (unsigned)(gridDim.x - 1));
    }
    __syncthreads();

    // ---- last block finalizes: sumPrior, final scalars, reset for next replay ----
    if (s_last) {
        float ps = 0.0f;
        for (int i = tid; i < NCLS; i += THREADS) ps += __ldg(prior + i);
        #pragma unroll
        for (int o = 16; o; o >>= 1) ps += __shfl_xor_sync(0xffffffffu, ps, o);
        if (lane == 0) s_red[warp] = ps;
        __syncthreads();
        if (tid == 0) {
            float sumP = 0.0f;
            #pragma unroll
            for (int i = 0; i < WARPS_PER_BLK; i++) sumP += s_red[i];

            const double S3 = *(volatile double*)&g_S3;
            const double S2 = *(volatile double*)&g_S2;
            const double CE = *(volatile double*)&g_CE;
            const unsigned long long nPll = *(volatile unsigned long long*)&g_nP;

            const double nP = (double)nPll;
            const double nU = (double)NROWS - nP;
            const float  C0 = logf(1.0f + EPSF);
            const double pu3 = S3 / fmax(1.0, nU) / (double)NCLS;
            const double pu2 = (S2 + (double)C0 * (double)sumP * nP) / fmax(1.0, nP);
            const double PULoss  = pu3 + pu2;
            const double PULossW = PULoss * 2.0;

            float cross, obj;
            if (nPll > 0ull) {
                cross = (float)(CE / nP);
                obj   = (float)(PULossW + (double)cross);
            } else {
                cross = __int_as_float(0x7fc00000);  // nan (0/0), reference picks PULoss
                obj   = (float)PULoss;
            }
            if (out_size >= 1) out[0] = obj;
            if (out_size >= 2) out[1] = (float)PULossW;
            if (out_size >= 3) out[2] = cross;

            // reset for next graph replay
            g_S3 = 0.0; g_S2 = 0.0; g_CE = 0.0; g_nP = 0ull;
            __threadfence();
            g_done = 0u;
        }
    }
}

extern "C" void kernel_launch(void* const* d_in, const int* in_sizes, int n_in,
                              void* d_out, int out_size) {
    const float* outputs   = (const float*)d_in[0];
    const int*   labels    = (const int*)d_in[1];
    const float* prior     = (const float*)d_in[2];
    const int*   indexlist = (const int*)d_in[3];

    mpuloss_fused<<<GRID_BLKS, THREADS>>>(outputs, labels, prior, indexlist,
                                          (float*)d_out, out_size);
}